// round 16
// baseline (speedup 1.0000x reference)
#include <cuda_runtime.h>
#include <cuda_fp16.h>
#include <math.h>
#include <stdint.h>

#define NHEADS 16
#define HD 64
#define DM 1024
#define PDIM 64
#define MAXS 2048
#define MAXB 2
#define L2E 1.4426950408889634f
#define PSTR 68     // P smem row stride (fp16x2 words); a-frag banks 4g+t distinct
#define VSTR 72     // V smem row stride (fp16x2 words); b-frag banks conflict-free

// scratch (device globals — no runtime allocation)
__device__ float g_masses[MAXB * NHEADS * MAXS];                 // [B,H,S]
__device__ float g_invd[(size_t)MAXS * MAXS];                    // 1 / dist_sq_mod
__device__ uint32_t g_O[(size_t)MAXB * MAXS * DM / 2];           // attn out, fp16x2
__device__ uint32_t g_Wc[(size_t)DM * DM / 2];                   // W_out, fp16x2

// ---------------- helpers ----------------
__device__ __forceinline__ float ex2(float v) {
    float y;
    asm("ex2.approx.ftz.f32 %0, %1;" : "=f"(y) : "f"(v));
    return y;
}
// fp16 m16n8k16, fp32 accum
__device__ __forceinline__ void mma_f16(float* d, const uint32_t* a, const uint32_t* b) {
    asm volatile(
        "mma.sync.aligned.m16n8k16.row.col.f32.f16.f16.f32 "
        "{%0,%1,%2,%3}, {%4,%5,%6,%7}, {%8,%9}, {%0,%1,%2,%3};"
        : "+f"(d[0]), "+f"(d[1]), "+f"(d[2]), "+f"(d[3])
        : "r"(a[0]), "r"(a[1]), "r"(a[2]), "r"(a[3]), "r"(b[0]), "r"(b[1]));
}

// ---------------------------------------------------------------------------
// Kernel 1: masses[b,h,s] = softplus( dot(xh[b,s,h,:], W_mass[h,:]) )
// ---------------------------------------------------------------------------
__global__ void mass_kernel(const float* __restrict__ x,
                            const float* __restrict__ Wm, int S) {
    int gw   = (blockIdx.x * 256 + threadIdx.x) >> 5;
    int lane = threadIdx.x & 31;
    int s = gw % S;
    int h = (gw / S) & (NHEADS - 1);
    int b = gw / (S * NHEADS);
    const float* xr = x + ((size_t)(b * S + s)) * DM + h * HD;
    float t = xr[lane] * Wm[h * HD + lane] + xr[lane + 32] * Wm[h * HD + lane + 32];
#pragma unroll
    for (int o = 16; o; o >>= 1) t += __shfl_xor_sync(0xffffffffu, t, o);
    if (lane == 0) {
        float m = (t > 20.f) ? t : log1pf(expf(t));
        g_masses[(b * NHEADS + h) * S + s] = m;
    }
}

// ---------------------------------------------------------------------------
// Kernel 1b: pre-convert W_out to fp16x2
// ---------------------------------------------------------------------------
__global__ void wcvt_kernel(const float* __restrict__ W) {
    int i = blockIdx.x * 256 + threadIdx.x;     // 8 floats / thread
    float4 v0 = *(const float4*)&W[(size_t)i * 8];
    float4 v1 = *(const float4*)&W[(size_t)i * 8 + 4];
    __half2 h0 = __floats2half2_rn(v0.x, v0.y);
    __half2 h1 = __floats2half2_rn(v0.z, v0.w);
    __half2 h2 = __floats2half2_rn(v1.x, v1.y);
    __half2 h3 = __floats2half2_rn(v1.z, v1.w);
    uint4 o;
    o.x = *(uint32_t*)&h0; o.y = *(uint32_t*)&h1;
    o.z = *(uint32_t*)&h2; o.w = *(uint32_t*)&h3;
    *(uint4*)&g_Wc[(size_t)i * 4] = o;
}

// ---------------------------------------------------------------------------
// Kernel 2: g_invd[i,j] = 1 / max( d2*(1+0.15*cos(sqrt(d2+1e-6))), 1e-6 )
// ---------------------------------------------------------------------------
__global__ void dist_kernel(const float* __restrict__ pos, int S) {
    __shared__ float Pi[PDIM][65];
    __shared__ float Pj[PDIM][65];
    int i0 = blockIdx.x * 64, j0 = blockIdx.y * 64;
    int tid = threadIdx.x;
#pragma unroll
    for (int v = 0; v < 16; v++) {
        int e = v * 256 + tid;
        int r = e >> 6, p = e & 63;
        Pi[p][r] = pos[(size_t)(i0 + r) * PDIM + p];
        Pj[p][r] = pos[(size_t)(j0 + r) * PDIM + p];
    }
    __syncthreads();
    int ty = tid >> 4, tx = tid & 15;
    float acc[4][4] = {};
#pragma unroll
    for (int p = 0; p < PDIM; p++) {
        float a[4], bb[4];
#pragma unroll
        for (int i = 0; i < 4; i++) a[i] = Pi[p][ty * 4 + i];
#pragma unroll
        for (int j = 0; j < 4; j++) bb[j] = Pj[p][tx * 4 + j];
#pragma unroll
        for (int i = 0; i < 4; i++)
#pragma unroll
            for (int j = 0; j < 4; j++) {
                float d = a[i] - bb[j];
                acc[i][j] = fmaf(d, d, acc[i][j]);
            }
    }
#pragma unroll
    for (int i = 0; i < 4; i++)
#pragma unroll
        for (int j = 0; j < 4; j++) {
            int ii = i0 + ty * 4 + i, jj = j0 + tx * 4 + j;
            float v = acc[i][j];
            float dn = sqrtf(v + 1e-6f);
            float d2 = v * (1.f + 0.15f * cosf(dn));
            d2 = fmaxf(d2, 1e-6f);
            g_invd[(size_t)ii * S + jj] = 1.0f / d2;
        }
}

// ---------------------------------------------------------------------------
// Kernel 3: attention in fp16 (P' = exp(f-50)), BOTH batches fused per CTA:
// g_invd is batch-independent, so each dv load now feeds 2x the exps/MMAs.
// 128-row i-tile, warp = 16 rows x 64 cols per batch (R10 inner loop x2).
// Grid = (S/128, NHEADS) = 256 CTAs = one full wave.
// ---------------------------------------------------------------------------
__global__ __launch_bounds__(256, 2)
void attn_kernel(const float* __restrict__ x,
                 const float* __restrict__ G, int S) {
    extern __shared__ char sm[];
    float* mi = (float*)sm;                          // [2][128] coefl-scaled
    uint32_t* Ph = (uint32_t*)(sm + 1024);           // [2][128*PSTR]
    uint32_t* Vb = Ph + 2 * 128 * PSTR;              // [2][64*VSTR]

    int h = blockIdx.y;
    int i0 = blockIdx.x * 128;
    int tid = threadIdx.x;
    int w = tid >> 5, lane = tid & 31;
    int g = lane >> 2, t = lane & 3;
    int wm = 16 * w;

    float coefl = fabsf(G[h]) * L2E;
    const float C50L = 50.0f * L2E;

    {   // i-tile masses, both batches, pre-scaled
        int bb = tid >> 7, r = tid & 127;
        mi[bb * 128 + r] = coefl * g_masses[(bb * NHEADS + h) * S + i0 + r];
    }
    __syncthreads();

    float acc[2][8][4] = {};
    float sacc[2][4] = {};
    int niter = S >> 7;

    for (int it = 0; it < niter; it++) {
        int jt = it << 7;

        // ---- V fill x2 batches: Vb[bb][k2][n] = {V[2k2][n], V[2k2+1][n]}
#pragma unroll
        for (int bb = 0; bb < 2; bb++) {
#pragma unroll
            for (int v4 = 0; v4 < 4; v4++) {
                int slot = v4 * 256 + tid;
                int n4 = slot & 15, k2 = slot >> 4;
                const float* xp = &x[((size_t)(bb * S + jt + 2 * k2)) * DM + h * HD + n4 * 4];
                float4 r0 = *(const float4*)xp;
                float4 r1 = *(const float4*)(xp + DM);
                __half2 h0 = __floats2half2_rn(r0.x, r1.x);
                __half2 h1 = __floats2half2_rn(r0.y, r1.y);
                __half2 h2 = __floats2half2_rn(r0.z, r1.z);
                __half2 h3 = __floats2half2_rn(r0.w, r1.w);
                uint4 o;
                o.x = *(uint32_t*)&h0; o.y = *(uint32_t*)&h1;
                o.z = *(uint32_t*)&h2; o.w = *(uint32_t*)&h3;
                *(uint4*)&Vb[bb * 64 * VSTR + k2 * VSTR + n4 * 4] = o;
            }
        }
        // ---- P gen: one dv load serves BOTH batches (the whole point)
        {
            float4 mv0 = *(const float4*)&g_masses[(size_t)h * S + jt + 4 * lane];
            float4 mv1 = *(const float4*)&g_masses[(size_t)(NHEADS + h) * S + jt + 4 * lane];
#pragma unroll
            for (int v = 0; v < 16; v++) {
                int r = v * 8 + w;
                float4 dv = *(const float4*)&g_invd[(size_t)(i0 + r) * S + jt + 4 * lane];
                float cm0 = mi[r];
                float e0 = ex2(fminf(cm0 * mv0.x * dv.x, C50L) - C50L);
                float e1 = ex2(fminf(cm0 * mv0.y * dv.y, C50L) - C50L);
                float e2 = ex2(fminf(cm0 * mv0.z * dv.z, C50L) - C50L);
                float e3 = ex2(fminf(cm0 * mv0.w * dv.w, C50L) - C50L);
                __half2 p0 = __floats2half2_rn(e0, e1);
                __half2 p1 = __floats2half2_rn(e2, e3);
                uint2 o;
                o.x = *(uint32_t*)&p0; o.y = *(uint32_t*)&p1;
                *(uint2*)&Ph[r * PSTR + 2 * lane] = o;
                float cm1 = mi[128 + r];
                float f0 = ex2(fminf(cm1 * mv1.x * dv.x, C50L) - C50L);
                float f1 = ex2(fminf(cm1 * mv1.y * dv.y, C50L) - C50L);
                float f2 = ex2(fminf(cm1 * mv1.z * dv.z, C50L) - C50L);
                float f3 = ex2(fminf(cm1 * mv1.w * dv.w, C50L) - C50L);
                __half2 q0 = __floats2half2_rn(f0, f1);
                __half2 q1 = __floats2half2_rn(f2, f3);
                uint2 o2;
                o2.x = *(uint32_t*)&q0; o2.y = *(uint32_t*)&q1;
                *(uint2*)&Ph[128 * PSTR + r * PSTR + 2 * lane] = o2;
            }
        }
        __syncthreads();   // tiles ready

        // ---- MMA x2 batches: 8 k16-chunks x (8 n-tiles + rowsum) each
#pragma unroll
        for (int kc = 0; kc < 8; kc++) {
            uint32_t ones[2] = {0x3C003C00u, 0x3C003C00u};
#pragma unroll
            for (int bb = 0; bb < 2; bb++) {
                const uint32_t* Pb = Ph + bb * 128 * PSTR;
                const uint32_t* Vv = Vb + bb * 64 * VSTR;
                uint32_t a[4];
                int ra = (wm + g) * PSTR + 8 * kc + t;
                int rb = ra + 8 * PSTR;
                a[0] = Pb[ra];     a[1] = Pb[rb];
                a[2] = Pb[ra + 4]; a[3] = Pb[rb + 4];
#pragma unroll
                for (int nt = 0; nt < 8; nt++) {
                    uint32_t br[2];
                    br[0] = Vv[(8 * kc + t) * VSTR + nt * 8 + g];
                    br[1] = Vv[(8 * kc + t + 4) * VSTR + nt * 8 + g];
                    mma_f16(acc[bb][nt], a, br);
                }
                mma_f16(sacc[bb], a, ones);
            }
        }
        __syncthreads();   // MMA reads done before next fill
    }

    // epilogue: both batches
#pragma unroll
    for (int bb = 0; bb < 2; bb++) {
        float r0 = 1.0f / sacc[bb][0];
        float r1 = 1.0f / sacc[bb][2];
        size_t w0 = (((size_t)(bb * S + i0 + wm + g)) * DM + h * HD) >> 1;
        size_t w1 = w0 + (size_t)4 * DM;   // +8 rows (fp16x2 words)
#pragma unroll
        for (int nt = 0; nt < 8; nt++) {
            __half2 o0 = __floats2half2_rn(acc[bb][nt][0] * r0, acc[bb][nt][1] * r0);
            __half2 o1 = __floats2half2_rn(acc[bb][nt][2] * r1, acc[bb][nt][3] * r1);
            g_O[w0 + nt * 4 + t] = *(uint32_t*)&o0;
            g_O[w1 + nt * 4 + t] = *(uint32_t*)&o1;
        }
    }
}

// ---------------------------------------------------------------------------
// Kernel 4: Y = O @ Wc^T, fp16 mma.sync m16n8k16, cp.async double-buffered.
// ---------------------------------------------------------------------------
__global__ __launch_bounds__(256, 2)
void out_gemm(float* __restrict__ Y) {
    extern __shared__ uint32_t sm_g[];
    uint32_t* As = sm_g;                 // [2][128][32] fp16x2 words
    uint32_t* Bs = sm_g + 2 * 128 * 32;

    int n0 = blockIdx.y * 128, j0 = blockIdx.x * 128;
    int tid = threadIdx.x;
    int w = tid >> 5, lane = tid & 31;
    int g = lane >> 2, t = lane & 3;
    int wm = (w >> 2) * 64, wn = (w & 3) * 32;
    int swz = g << 2;

    float acc[4][4][4] = {};

    int cr[4], cc[4];
#pragma unroll
    for (int v = 0; v < 4; v++) {
        int idx4 = v * 256 + tid;
        cr[v] = idx4 >> 3;
        cc[v] = (idx4 & 7) * 4;
    }

#define OG_ISSUE(buf, k0w)                                                       \
    do {                                                                         \
        _Pragma("unroll")                                                        \
        for (int v = 0; v < 4; v++) {                                            \
            int r = cr[v], c = cc[v];                                            \
            int so = r * 32 + (c ^ ((r & 7) << 2));                              \
            uint32_t dA = (uint32_t)__cvta_generic_to_shared(&As[(buf)*4096 + so]); \
            const uint32_t* sA = &g_O[(size_t)(n0 + r) * (DM / 2) + (k0w) + c];  \
            asm volatile("cp.async.cg.shared.global [%0], [%1], 16;" ::"r"(dA), "l"(sA)); \
            uint32_t dB = (uint32_t)__cvta_generic_to_shared(&Bs[(buf)*4096 + so]); \
            const uint32_t* sB = &g_Wc[(size_t)(j0 + r) * (DM / 2) + (k0w) + c]; \
            asm volatile("cp.async.cg.shared.global [%0], [%1], 16;" ::"r"(dB), "l"(sB)); \
        }                                                                        \
        asm volatile("cp.async.commit_group;");                                  \
    } while (0)

    OG_ISSUE(0, 0);

    for (int ki = 0; ki < DM / 64; ki++) {
        asm volatile("cp.async.wait_group 0;");
        __syncthreads();
        if (ki + 1 < DM / 64) OG_ISSUE((ki + 1) & 1, (ki + 1) * 32);

        const uint32_t* Ab = &As[(ki & 1) * 4096];
        const uint32_t* Bb = &Bs[(ki & 1) * 4096];
#pragma unroll
        for (int ks = 0; ks < 4; ks++) {
            int k = ks * 8;
            uint32_t a[4][4], bf[4][2];
#pragma unroll
            for (int mt = 0; mt < 4; mt++) {
                int r = wm + mt * 16 + g;
                a[mt][0] = Ab[r * 32 + ((k + t) ^ swz)];
                a[mt][1] = Ab[(r + 8) * 32 + ((k + t) ^ swz)];
                a[mt][2] = Ab[r * 32 + ((k + t + 4) ^ swz)];
                a[mt][3] = Ab[(r + 8) * 32 + ((k + t + 4) ^ swz)];
            }
#pragma unroll
            for (int nt = 0; nt < 4; nt++) {
                int r = wn + nt * 8 + g;
                bf[nt][0] = Bb[r * 32 + ((k + t) ^ swz)];
                bf[nt][1] = Bb[r * 32 + ((k + t + 4) ^ swz)];
            }
#pragma unroll
            for (int mt = 0; mt < 4; mt++)
#pragma unroll
                for (int nt = 0; nt < 4; nt++)
                    mma_f16(acc[mt][nt], a[mt], bf[nt]);
        }
    }
#pragma unroll
    for (int mt = 0; mt < 4; mt++) {
        int m = n0 + wm + mt * 16 + g;
#pragma unroll
        for (int nt = 0; nt < 4; nt++) {
            int j = j0 + wn + nt * 8 + 2 * t;
            float2 v0, v1;
            v0.x = acc[mt][nt][0]; v0.y = acc[mt][nt][1];
            v1.x = acc[mt][nt][2]; v1.y = acc[mt][nt][3];
            *(float2*)&Y[(size_t)m * DM + j] = v0;
            *(float2*)&Y[(size_t)(m + 8) * DM + j] = v1;
        }
    }
}

// ---------------------------------------------------------------------------
extern "C" void kernel_launch(void* const* d_in, const int* in_sizes, int n_in,
                              void* d_out, int out_size) {
    const float* x   = (const float*)d_in[0];   // [B,S,1024]
    const float* pos = (const float*)d_in[1];   // [S,64]
    const float* Wm  = (const float*)d_in[2];   // [16,64]
    const float* G   = (const float*)d_in[3];   // [16]
    const float* Wo  = (const float*)d_in[4];   // [1024,1024]
    float* out = (float*)d_out;                 // [B,S,1024]

    int S = in_sizes[1] / PDIM;
    int B = in_sizes[0] / (S * DM);

    int ATTN_SMEM = 1024 + 2 * 128 * PSTR * 4 + 2 * 64 * VSTR * 4;
    static const int GEMM_SMEM = 4 * 128 * 32 * 4;
    cudaFuncSetAttribute(attn_kernel, cudaFuncAttributeMaxDynamicSharedMemorySize, ATTN_SMEM);
    cudaFuncSetAttribute(out_gemm, cudaFuncAttributeMaxDynamicSharedMemorySize, GEMM_SMEM);

    int nwarps = B * NHEADS * S;
    mass_kernel<<<nwarps / 8, 256>>>(x, Wm, S);

    wcvt_kernel<<<DM * DM / 2048, 256>>>(Wo);

    dim3 gd(S / 64, S / 64);
    dist_kernel<<<gd, 256>>>(pos, S);

    dim3 ga(S / 128, NHEADS);
    attn_kernel<<<ga, 256, ATTN_SMEM>>>(x, G, S);

    dim3 gg(DM / 128, (B * S) / 128);
    out_gemm<<<gg, 256, GEMM_SMEM>>>(out);
}

// round 17
// speedup vs baseline: 1.1777x; 1.1777x over previous
#include <cuda_runtime.h>
#include <cuda_fp16.h>
#include <math.h>
#include <stdint.h>

#define NHEADS 16
#define HD 64
#define DM 1024
#define PDIM 64
#define MAXS 2048
#define MAXB 2
#define L2E 1.4426950408889634f
#define PSTR 68     // P smem row stride (fp16x2 words); a-frag banks 4g+t distinct
#define VSTR 72     // V smem row stride (fp16x2 words); b-frag banks conflict-free

// scratch (device globals — no runtime allocation)
__device__ float g_masses[MAXB * NHEADS * MAXS];                 // [B,H,S]
__device__ float g_invd[(size_t)MAXS * MAXS];                    // 1 / dist_sq_mod
__device__ uint32_t g_O[(size_t)MAXB * MAXS * DM / 2];           // attn out, fp16x2
__device__ uint32_t g_Wc[(size_t)DM * DM / 2];                   // W_out, fp16x2

// ---------------- helpers ----------------
__device__ __forceinline__ float ex2(float v) {
    float y;
    asm("ex2.approx.ftz.f32 %0, %1;" : "=f"(y) : "f"(v));
    return y;
}
// fp16 m16n8k16, fp32 accum
__device__ __forceinline__ void mma_f16(float* d, const uint32_t* a, const uint32_t* b) {
    asm volatile(
        "mma.sync.aligned.m16n8k16.row.col.f32.f16.f16.f32 "
        "{%0,%1,%2,%3}, {%4,%5,%6,%7}, {%8,%9}, {%0,%1,%2,%3};"
        : "+f"(d[0]), "+f"(d[1]), "+f"(d[2]), "+f"(d[3])
        : "r"(a[0]), "r"(a[1]), "r"(a[2]), "r"(a[3]), "r"(b[0]), "r"(b[1]));
}

// ---------------------------------------------------------------------------
// Kernel 1: masses[b,h,s] = softplus( dot(xh[b,s,h,:], W_mass[h,:]) )
// ---------------------------------------------------------------------------
__global__ void mass_kernel(const float* __restrict__ x,
                            const float* __restrict__ Wm, int S) {
    int gw   = (blockIdx.x * 256 + threadIdx.x) >> 5;
    int lane = threadIdx.x & 31;
    int s = gw % S;
    int h = (gw / S) & (NHEADS - 1);
    int b = gw / (S * NHEADS);
    const float* xr = x + ((size_t)(b * S + s)) * DM + h * HD;
    float t = xr[lane] * Wm[h * HD + lane] + xr[lane + 32] * Wm[h * HD + lane + 32];
#pragma unroll
    for (int o = 16; o; o >>= 1) t += __shfl_xor_sync(0xffffffffu, t, o);
    if (lane == 0) {
        float m = (t > 20.f) ? t : log1pf(expf(t));
        g_masses[(b * NHEADS + h) * S + s] = m;
    }
}

// ---------------------------------------------------------------------------
// Kernel 1b: pre-convert W_out to fp16x2
// ---------------------------------------------------------------------------
__global__ void wcvt_kernel(const float* __restrict__ W) {
    int i = blockIdx.x * 256 + threadIdx.x;     // 8 floats / thread
    float4 v0 = *(const float4*)&W[(size_t)i * 8];
    float4 v1 = *(const float4*)&W[(size_t)i * 8 + 4];
    __half2 h0 = __floats2half2_rn(v0.x, v0.y);
    __half2 h1 = __floats2half2_rn(v0.z, v0.w);
    __half2 h2 = __floats2half2_rn(v1.x, v1.y);
    __half2 h3 = __floats2half2_rn(v1.z, v1.w);
    uint4 o;
    o.x = *(uint32_t*)&h0; o.y = *(uint32_t*)&h1;
    o.z = *(uint32_t*)&h2; o.w = *(uint32_t*)&h3;
    *(uint4*)&g_Wc[(size_t)i * 4] = o;
}

// ---------------------------------------------------------------------------
// Kernel 2: g_invd[i,j] = 1 / max( d2*(1+0.15*cos(sqrt(d2+1e-6))), 1e-6 )
// ---------------------------------------------------------------------------
__global__ void dist_kernel(const float* __restrict__ pos, int S) {
    __shared__ float Pi[PDIM][65];
    __shared__ float Pj[PDIM][65];
    int i0 = blockIdx.x * 64, j0 = blockIdx.y * 64;
    int tid = threadIdx.x;
#pragma unroll
    for (int v = 0; v < 16; v++) {
        int e = v * 256 + tid;
        int r = e >> 6, p = e & 63;
        Pi[p][r] = pos[(size_t)(i0 + r) * PDIM + p];
        Pj[p][r] = pos[(size_t)(j0 + r) * PDIM + p];
    }
    __syncthreads();
    int ty = tid >> 4, tx = tid & 15;
    float acc[4][4] = {};
#pragma unroll
    for (int p = 0; p < PDIM; p++) {
        float a[4], bb[4];
#pragma unroll
        for (int i = 0; i < 4; i++) a[i] = Pi[p][ty * 4 + i];
#pragma unroll
        for (int j = 0; j < 4; j++) bb[j] = Pj[p][tx * 4 + j];
#pragma unroll
        for (int i = 0; i < 4; i++)
#pragma unroll
            for (int j = 0; j < 4; j++) {
                float d = a[i] - bb[j];
                acc[i][j] = fmaf(d, d, acc[i][j]);
            }
    }
#pragma unroll
    for (int i = 0; i < 4; i++)
#pragma unroll
        for (int j = 0; j < 4; j++) {
            int ii = i0 + ty * 4 + i, jj = j0 + tx * 4 + j;
            float v = acc[i][j];
            float dn = sqrtf(v + 1e-6f);
            float d2 = v * (1.f + 0.15f * cosf(dn));
            d2 = fmaxf(d2, 1e-6f);
            g_invd[(size_t)ii * S + jj] = 1.0f / d2;
        }
}

// ---------------------------------------------------------------------------
// Kernel 3: attention in fp16 (P' = exp(f-50)). 256-row i-tile, warp = 32
// rows x 64 cols (two m16 blocks share B fragments). R12 structure exactly;
// the ONLY change vs R12: dv (invd row) is software-prefetched one row ahead
// in P-gen so each LDG.128 overlaps the previous row's exp/cvt/STS chain.
// ---------------------------------------------------------------------------
__global__ __launch_bounds__(256, 2)
void attn_kernel(const float* __restrict__ x,
                 const float* __restrict__ G, int S) {
    extern __shared__ char sm[];
    float* ms = (float*)sm;                          // [S]
    uint32_t* Ph = (uint32_t*)(sm + (size_t)S * 4);  // [256][PSTR] fp16x2 (j pairs)
    uint32_t* Vb = Ph + 256 * PSTR;                  // [64][VSTR]  fp16x2 (k pairs)

    int bh = blockIdx.y;
    int b = bh >> 4, h = bh & 15;
    int i0 = blockIdx.x * 256;
    int tid = threadIdx.x;
    int w = tid >> 5, lane = tid & 31;
    int g = lane >> 2, t = lane & 3;
    int wm = 32 * w;
    int bS = b * S;

    const float* mrow = &g_masses[(b * NHEADS + h) * S];
    for (int i = tid; i < S; i += 256) ms[i] = mrow[i];
    __syncthreads();

    float coefl = fabsf(G[h]) * L2E;
    const float C50L = 50.0f * L2E;

    float acc[2][8][4] = {};
    float sacc[2][4] = {};
    int niter = S >> 7;

    for (int it = 0; it < niter; it++) {
        int jt = it << 7;

        // ---- V fill (R12 layout): Vb[k2][n] = {V[2k2][n], V[2k2+1][n]} fp16x2
#pragma unroll
        for (int v4 = 0; v4 < 4; v4++) {
            int slot = v4 * 256 + tid;
            int n4 = slot & 15, k2 = slot >> 4;
            const float* xp = &x[((size_t)(bS + jt + 2 * k2)) * DM + h * HD + n4 * 4];
            float4 r0 = *(const float4*)xp;
            float4 r1 = *(const float4*)(xp + DM);
            __half2 h0 = __floats2half2_rn(r0.x, r1.x);
            __half2 h1 = __floats2half2_rn(r0.y, r1.y);
            __half2 h2 = __floats2half2_rn(r0.z, r1.z);
            __half2 h3 = __floats2half2_rn(r0.w, r1.w);
            uint4 o;
            o.x = *(uint32_t*)&h0; o.y = *(uint32_t*)&h1;
            o.z = *(uint32_t*)&h2; o.w = *(uint32_t*)&h3;
            *(uint4*)&Vb[k2 * VSTR + n4 * 4] = o;
        }
        // ---- P gen: 256 rows; row per (v,w); 4 cols/thread; dv prefetched
        {
            const float* dbase = &g_invd[(size_t)(i0 + w) * S + jt + 4 * lane];
            float4 dv = *(const float4*)dbase;               // row v=0
#pragma unroll
            for (int v = 0; v < 32; v++) {
                float4 dv_cur = dv;
                if (v < 31)                                   // prefetch row v+1
                    dv = *(const float4*)(dbase + (size_t)(v + 1) * 8 * S);
                int r = v * 8 + w;
                float cm = coefl * ms[i0 + r];
                float4 mv = *(const float4*)&ms[jt + 4 * lane];
                float e0 = ex2(fminf(cm * mv.x * dv_cur.x, C50L) - C50L);
                float e1 = ex2(fminf(cm * mv.y * dv_cur.y, C50L) - C50L);
                float e2 = ex2(fminf(cm * mv.z * dv_cur.z, C50L) - C50L);
                float e3 = ex2(fminf(cm * mv.w * dv_cur.w, C50L) - C50L);
                __half2 p0 = __floats2half2_rn(e0, e1);
                __half2 p1 = __floats2half2_rn(e2, e3);
                uint2 o;
                o.x = *(uint32_t*)&p0; o.y = *(uint32_t*)&p1;
                *(uint2*)&Ph[r * PSTR + 2 * lane] = o;
            }
        }
        __syncthreads();   // tiles ready

        // ---- MMA (R12 exactly): 8 k16-chunks x (8 n x 2 m + 2 rowsums)
#pragma unroll
        for (int kc = 0; kc < 8; kc++) {
            uint32_t a0[4], a1[4];
            int ra = (wm + g) * PSTR + 8 * kc + t;
            a0[0] = Ph[ra];              a0[1] = Ph[ra + 8 * PSTR];
            a0[2] = Ph[ra + 4];          a0[3] = Ph[ra + 8 * PSTR + 4];
            int rb = ra + 16 * PSTR;
            a1[0] = Ph[rb];              a1[1] = Ph[rb + 8 * PSTR];
            a1[2] = Ph[rb + 4];          a1[3] = Ph[rb + 8 * PSTR + 4];
#pragma unroll
            for (int nt = 0; nt < 8; nt++) {
                uint32_t br[2];
                br[0] = Vb[(8 * kc + t) * VSTR + nt * 8 + g];
                br[1] = Vb[(8 * kc + t + 4) * VSTR + nt * 8 + g];
                mma_f16(acc[0][nt], a0, br);
                mma_f16(acc[1][nt], a1, br);
            }
            uint32_t ones[2] = {0x3C003C00u, 0x3C003C00u};
            mma_f16(sacc[0], a0, ones);
            mma_f16(sacc[1], a1, ones);
        }
        __syncthreads();   // MMA reads done before next fill
    }

    // epilogue: two m16 blocks per warp
#pragma unroll
    for (int mb = 0; mb < 2; mb++) {
        float r0 = 1.0f / sacc[mb][0];
        float r1 = 1.0f / sacc[mb][2];
        size_t w0 = (((size_t)(bS + i0 + wm + 16 * mb + g)) * DM + h * HD) >> 1;
        size_t w1 = w0 + (size_t)4 * DM;   // +8 rows (fp16x2 words)
#pragma unroll
        for (int nt = 0; nt < 8; nt++) {
            __half2 o0 = __floats2half2_rn(acc[mb][nt][0] * r0, acc[mb][nt][1] * r0);
            __half2 o1 = __floats2half2_rn(acc[mb][nt][2] * r1, acc[mb][nt][3] * r1);
            g_O[w0 + nt * 4 + t] = *(uint32_t*)&o0;
            g_O[w1 + nt * 4 + t] = *(uint32_t*)&o1;
        }
    }
}

// ---------------------------------------------------------------------------
// Kernel 4: Y = O @ Wc^T, fp16 mma.sync m16n8k16, cp.async double-buffered.
// ---------------------------------------------------------------------------
__global__ __launch_bounds__(256, 2)
void out_gemm(float* __restrict__ Y) {
    extern __shared__ uint32_t sm_g[];
    uint32_t* As = sm_g;                 // [2][128][32] fp16x2 words
    uint32_t* Bs = sm_g + 2 * 128 * 32;

    int n0 = blockIdx.y * 128, j0 = blockIdx.x * 128;
    int tid = threadIdx.x;
    int w = tid >> 5, lane = tid & 31;
    int g = lane >> 2, t = lane & 3;
    int wm = (w >> 2) * 64, wn = (w & 3) * 32;
    int swz = g << 2;

    float acc[4][4][4] = {};

    int cr[4], cc[4];
#pragma unroll
    for (int v = 0; v < 4; v++) {
        int idx4 = v * 256 + tid;
        cr[v] = idx4 >> 3;
        cc[v] = (idx4 & 7) * 4;
    }

#define OG_ISSUE(buf, k0w)                                                       \
    do {                                                                         \
        _Pragma("unroll")                                                        \
        for (int v = 0; v < 4; v++) {                                            \
            int r = cr[v], c = cc[v];                                            \
            int so = r * 32 + (c ^ ((r & 7) << 2));                              \
            uint32_t dA = (uint32_t)__cvta_generic_to_shared(&As[(buf)*4096 + so]); \
            const uint32_t* sA = &g_O[(size_t)(n0 + r) * (DM / 2) + (k0w) + c];  \
            asm volatile("cp.async.cg.shared.global [%0], [%1], 16;" ::"r"(dA), "l"(sA)); \
            uint32_t dB = (uint32_t)__cvta_generic_to_shared(&Bs[(buf)*4096 + so]); \
            const uint32_t* sB = &g_Wc[(size_t)(j0 + r) * (DM / 2) + (k0w) + c]; \
            asm volatile("cp.async.cg.shared.global [%0], [%1], 16;" ::"r"(dB), "l"(sB)); \
        }                                                                        \
        asm volatile("cp.async.commit_group;");                                  \
    } while (0)

    OG_ISSUE(0, 0);

    for (int ki = 0; ki < DM / 64; ki++) {
        asm volatile("cp.async.wait_group 0;");
        __syncthreads();
        if (ki + 1 < DM / 64) OG_ISSUE((ki + 1) & 1, (ki + 1) * 32);

        const uint32_t* Ab = &As[(ki & 1) * 4096];
        const uint32_t* Bb = &Bs[(ki & 1) * 4096];
#pragma unroll
        for (int ks = 0; ks < 4; ks++) {
            int k = ks * 8;
            uint32_t a[4][4], bf[4][2];
#pragma unroll
            for (int mt = 0; mt < 4; mt++) {
                int r = wm + mt * 16 + g;
                a[mt][0] = Ab[r * 32 + ((k + t) ^ swz)];
                a[mt][1] = Ab[(r + 8) * 32 + ((k + t) ^ swz)];
                a[mt][2] = Ab[r * 32 + ((k + t + 4) ^ swz)];
                a[mt][3] = Ab[(r + 8) * 32 + ((k + t + 4) ^ swz)];
            }
#pragma unroll
            for (int nt = 0; nt < 4; nt++) {
                int r = wn + nt * 8 + g;
                bf[nt][0] = Bb[r * 32 + ((k + t) ^ swz)];
                bf[nt][1] = Bb[r * 32 + ((k + t + 4) ^ swz)];
            }
#pragma unroll
            for (int mt = 0; mt < 4; mt++)
#pragma unroll
                for (int nt = 0; nt < 4; nt++)
                    mma_f16(acc[mt][nt], a[mt], bf[nt]);
        }
    }
#pragma unroll
    for (int mt = 0; mt < 4; mt++) {
        int m = n0 + wm + mt * 16 + g;
#pragma unroll
        for (int nt = 0; nt < 4; nt++) {
            int j = j0 + wn + nt * 8 + 2 * t;
            float2 v0, v1;
            v0.x = acc[mt][nt][0]; v0.y = acc[mt][nt][1];
            v1.x = acc[mt][nt][2]; v1.y = acc[mt][nt][3];
            *(float2*)&Y[(size_t)m * DM + j] = v0;
            *(float2*)&Y[(size_t)(m + 8) * DM + j] = v1;
        }
    }
}

// ---------------------------------------------------------------------------
extern "C" void kernel_launch(void* const* d_in, const int* in_sizes, int n_in,
                              void* d_out, int out_size) {
    const float* x   = (const float*)d_in[0];   // [B,S,1024]
    const float* pos = (const float*)d_in[1];   // [S,64]
    const float* Wm  = (const float*)d_in[2];   // [16,64]
    const float* G   = (const float*)d_in[3];   // [16]
    const float* Wo  = (const float*)d_in[4];   // [1024,1024]
    float* out = (float*)d_out;                 // [B,S,1024]

    int S = in_sizes[1] / PDIM;
    int B = in_sizes[0] / (S * DM);

    int ATTN_SMEM = S * 4 + 256 * PSTR * 4 + 64 * VSTR * 4;
    static const int GEMM_SMEM = 4 * 128 * 32 * 4;
    cudaFuncSetAttribute(attn_kernel, cudaFuncAttributeMaxDynamicSharedMemorySize, ATTN_SMEM);
    cudaFuncSetAttribute(out_gemm, cudaFuncAttributeMaxDynamicSharedMemorySize, GEMM_SMEM);

    int nwarps = B * NHEADS * S;
    mass_kernel<<<nwarps / 8, 256>>>(x, Wm, S);

    wcvt_kernel<<<DM * DM / 2048, 256>>>(Wo);

    dim3 gd(S / 64, S / 64);
    dist_kernel<<<gd, 256>>>(pos, S);

    dim3 ga(S / 256, B * NHEADS);
    attn_kernel<<<ga, 256, ATTN_SMEM>>>(x, G, S);

    dim3 gg(DM / 128, (B * S) / 128);
    out_gemm<<<gg, 256, GEMM_SMEM>>>(out);
}